// round 2
// baseline (speedup 1.0000x reference)
#include <cuda_runtime.h>
#include <cuda_bf16.h>
#include <cstddef>

// Problem constants
#define BATCH 8
#define SEQ   2048
#define DIM   1024

// ---------------------------------------------------------------------------
// Scratch (allocation-free: __device__ globals)
// ---------------------------------------------------------------------------
__device__ float g_Q2[(size_t)BATCH * SEQ * DIM];           // 64 MB
__device__ float g_K2[(size_t)BATCH * SEQ * DIM];           // 64 MB
__device__ float g_V [(size_t)BATCH * SEQ * DIM];           // 64 MB
__device__ float g_P [(size_t)BATCH * SEQ * SEQ];           // 134 MB (scores/probs)
__device__ float g_vconst[BATCH * DIM];
__device__ float g_corr  [BATCH * DIM];

// ---------------------------------------------------------------------------
// vconst[b,n] = X1[b,:] @ Wv[0:D, n] + bv[n]
// grid (DIM/256, BATCH), block 256
// ---------------------------------------------------------------------------
__global__ __launch_bounds__(256) void vconst_kernel(
    const float* __restrict__ X1, const float* __restrict__ Wv,
    const float* __restrict__ bv, float* __restrict__ vconst)
{
    int n = blockIdx.x * 256 + threadIdx.x;
    int b = blockIdx.y;
    const float* x = X1 + b * DIM;
    float acc = bv[n];
    #pragma unroll 8
    for (int d = 0; d < DIM; d++)
        acc += x[d] * Wv[(size_t)d * DIM + n];
    vconst[b * DIM + n] = acc;
}

// ---------------------------------------------------------------------------
// corr[b,n] = -(alpha/SEQ) * sum_k V[b,k,n]
// grid (DIM/256, BATCH), block 256
// ---------------------------------------------------------------------------
__global__ __launch_bounds__(256) void colsum_kernel(
    const float* __restrict__ V, const float* __restrict__ alpha,
    float* __restrict__ corr)
{
    int n = blockIdx.x * 256 + threadIdx.x;
    int b = blockIdx.y;
    const float* p = V + (size_t)b * SEQ * DIM + n;
    float s0 = 0.f, s1 = 0.f, s2 = 0.f, s3 = 0.f;
    #pragma unroll 4
    for (int k = 0; k < SEQ; k += 4) {
        s0 += p[(size_t)(k + 0) * DIM];
        s1 += p[(size_t)(k + 1) * DIM];
        s2 += p[(size_t)(k + 2) * DIM];
        s3 += p[(size_t)(k + 3) * DIM];
    }
    corr[b * DIM + n] = -(alpha[0] / (float)SEQ) * ((s0 + s1) + (s2 + s3));
}

// ---------------------------------------------------------------------------
// Tiled SGEMM, 128x128 block tile, BK=16, 8x8 per thread, 256 threads.
// C = scale * (A @ B) + bias_row   (bias may be null -> 0)
// NN: A [M,K] row-major, B [K,N] row-major
// Batch via blockIdx.z with element strides sA/sB/sC/sBias.
// All dims assumed divisible by tile sizes (true for this problem).
// ---------------------------------------------------------------------------
#define BM 128
#define BN 128
#define BK 16
#define TM 8
#define TN 8
#define PAD 4

__global__ __launch_bounds__(256) void sgemm_nn(
    const float* __restrict__ A, const float* __restrict__ B,
    float* __restrict__ C, const float* __restrict__ bias,
    int N, int K, float scale,
    size_t sA, size_t sB, size_t sC, size_t sBias)
{
    __shared__ float As[BK][BM + PAD];
    __shared__ float Bs[BK][BN + PAD];

    const int z = blockIdx.z;
    A += (size_t)z * sA;
    B += (size_t)z * sB;
    C += (size_t)z * sC;
    const float* biasp = bias ? bias + (size_t)z * sBias : nullptr;

    const int tid  = threadIdx.x;
    const int brow = blockIdx.y * BM;
    const int bcol = blockIdx.x * BN;
    const int tr = (tid >> 4) * TM;   // 0..120
    const int tc = (tid & 15) * TN;   // 0..120

    // A-tile load mapping (transpose into smem): 128 rows x 16 cols
    const int a_row  = tid >> 2;        // 0..63 (two iters: +64)
    const int a_col4 = (tid & 3) * 4;   // 0,4,8,12
    // B-tile load mapping (direct float4): 16 rows x 128 cols
    const int b_row  = tid >> 5;        // 0..7 (two iters: +8)
    const int b_col4 = (tid & 31) * 4;  // 0..124

    float acc[TM][TN];
    #pragma unroll
    for (int i = 0; i < TM; i++)
        #pragma unroll
        for (int j = 0; j < TN; j++) acc[i][j] = 0.f;

    for (int k0 = 0; k0 < K; k0 += BK) {
        #pragma unroll
        for (int it = 0; it < 2; it++) {
            int r = a_row + it * 64;
            float4 v = *(const float4*)(A + (size_t)(brow + r) * K + k0 + a_col4);
            As[a_col4 + 0][r] = v.x;
            As[a_col4 + 1][r] = v.y;
            As[a_col4 + 2][r] = v.z;
            As[a_col4 + 3][r] = v.w;
        }
        #pragma unroll
        for (int it = 0; it < 2; it++) {
            int r = b_row + it * 8;
            *(float4*)(&Bs[r][b_col4]) =
                *(const float4*)(B + (size_t)(k0 + r) * N + bcol + b_col4);
        }
        __syncthreads();

        #pragma unroll
        for (int kk = 0; kk < BK; kk++) {
            float a[TM], bb[TN];
            #pragma unroll
            for (int i = 0; i < TM; i++) a[i] = As[kk][tr + i];
            #pragma unroll
            for (int j = 0; j < TN; j++) bb[j] = Bs[kk][tc + j];
            #pragma unroll
            for (int i = 0; i < TM; i++)
                #pragma unroll
                for (int j = 0; j < TN; j++)
                    acc[i][j] += a[i] * bb[j];
        }
        __syncthreads();
    }

    float bvreg[TN];
    #pragma unroll
    for (int j = 0; j < TN; j++)
        bvreg[j] = biasp ? biasp[bcol + tc + j] : 0.f;

    #pragma unroll
    for (int i = 0; i < TM; i++) {
        size_t crow = (size_t)(brow + tr + i) * N + bcol + tc;
        #pragma unroll
        for (int jj = 0; jj < TN; jj += 4) {
            float4 o;
            o.x = fmaf(acc[i][jj + 0], scale, bvreg[jj + 0]);
            o.y = fmaf(acc[i][jj + 1], scale, bvreg[jj + 1]);
            o.z = fmaf(acc[i][jj + 2], scale, bvreg[jj + 2]);
            o.w = fmaf(acc[i][jj + 3], scale, bvreg[jj + 3]);
            *(float4*)(C + crow + jj) = o;
        }
    }
}

// NT variant: C[i,j] = scale * sum_d A[i,d]*B[j,d]   (both row-major [.,K])
__global__ __launch_bounds__(256) void sgemm_nt(
    const float* __restrict__ A, const float* __restrict__ B,
    float* __restrict__ C,
    int N, int K, float scale,
    size_t sA, size_t sB, size_t sC)
{
    __shared__ float As[BK][BM + PAD];
    __shared__ float Bs[BK][BN + PAD];

    const int z = blockIdx.z;
    A += (size_t)z * sA;
    B += (size_t)z * sB;
    C += (size_t)z * sC;

    const int tid  = threadIdx.x;
    const int brow = blockIdx.y * BM;
    const int bcol = blockIdx.x * BN;
    const int tr = (tid >> 4) * TM;
    const int tc = (tid & 15) * TN;

    const int l_row  = tid >> 2;        // 0..63
    const int l_col4 = (tid & 3) * 4;   // 0,4,8,12

    float acc[TM][TN];
    #pragma unroll
    for (int i = 0; i < TM; i++)
        #pragma unroll
        for (int j = 0; j < TN; j++) acc[i][j] = 0.f;

    for (int k0 = 0; k0 < K; k0 += BK) {
        #pragma unroll
        for (int it = 0; it < 2; it++) {
            int r = l_row + it * 64;
            float4 v = *(const float4*)(A + (size_t)(brow + r) * K + k0 + l_col4);
            As[l_col4 + 0][r] = v.x;
            As[l_col4 + 1][r] = v.y;
            As[l_col4 + 2][r] = v.z;
            As[l_col4 + 3][r] = v.w;
        }
        #pragma unroll
        for (int it = 0; it < 2; it++) {
            int r = l_row + it * 64;
            float4 v = *(const float4*)(B + (size_t)(bcol + r) * K + k0 + l_col4);
            Bs[l_col4 + 0][r] = v.x;
            Bs[l_col4 + 1][r] = v.y;
            Bs[l_col4 + 2][r] = v.z;
            Bs[l_col4 + 3][r] = v.w;
        }
        __syncthreads();

        #pragma unroll
        for (int kk = 0; kk < BK; kk++) {
            float a[TM], bb[TN];
            #pragma unroll
            for (int i = 0; i < TM; i++) a[i] = As[kk][tr + i];
            #pragma unroll
            for (int j = 0; j < TN; j++) bb[j] = Bs[kk][tc + j];
            #pragma unroll
            for (int i = 0; i < TM; i++)
                #pragma unroll
                for (int j = 0; j < TN; j++)
                    acc[i][j] += a[i] * bb[j];
        }
        __syncthreads();
    }

    #pragma unroll
    for (int i = 0; i < TM; i++) {
        size_t crow = (size_t)(brow + tr + i) * N + bcol + tc;
        #pragma unroll
        for (int jj = 0; jj < TN; jj += 4) {
            float4 o;
            o.x = acc[i][jj + 0] * scale;
            o.y = acc[i][jj + 1] * scale;
            o.z = acc[i][jj + 2] * scale;
            o.w = acc[i][jj + 3] * scale;
            *(float4*)(C + crow + jj) = o;
        }
    }
}

// ---------------------------------------------------------------------------
// In-place row softmax over SEQ=2048 columns. One block (256 thr) per row.
// ---------------------------------------------------------------------------
__global__ __launch_bounds__(256) void softmax_kernel(float* __restrict__ P)
{
    float* row = P + (size_t)blockIdx.x * SEQ;
    const int tid = threadIdx.x;

    float v[8];
    float m = -1e30f;
    #pragma unroll
    for (int i = 0; i < 8; i++) {
        v[i] = row[tid + 256 * i];
        m = fmaxf(m, v[i]);
    }
    #pragma unroll
    for (int o = 16; o > 0; o >>= 1)
        m = fmaxf(m, __shfl_xor_sync(0xFFFFFFFFu, m, o));

    __shared__ float redm[8];
    __shared__ float reds[8];
    if ((tid & 31) == 0) redm[tid >> 5] = m;
    __syncthreads();
    m = redm[0];
    #pragma unroll
    for (int i = 1; i < 8; i++) m = fmaxf(m, redm[i]);

    float s = 0.f;
    #pragma unroll
    for (int i = 0; i < 8; i++) {
        v[i] = __expf(v[i] - m);
        s += v[i];
    }
    #pragma unroll
    for (int o = 16; o > 0; o >>= 1)
        s += __shfl_xor_sync(0xFFFFFFFFu, s, o);
    if ((tid & 31) == 0) reds[tid >> 5] = s;
    __syncthreads();
    s = reds[0];
    #pragma unroll
    for (int i = 1; i < 8; i++) s += reds[i];

    float inv = 1.f / s;
    #pragma unroll
    for (int i = 0; i < 8; i++)
        row[tid + 256 * i] = v[i] * inv;
}

// ---------------------------------------------------------------------------
// Launch
// Inputs (metadata order):
//  0 X1 [8,1024]   1 X2 [8,2048,1024]
//  2 Wq1 3 bq1 4 Wq2 5 bq2 6 Wk1 7 bk1 8 Wk2 9 bk2   (Wq1/bq1/Wk1/bk1 unused:
//     softmax of a row-constant score matrix is uniform 1/S)
//  10 Wv [2048,1024]  11 bv [1024]  12 alpha [1]
// Output: [8,2048,1024] float32
// ---------------------------------------------------------------------------
extern "C" void kernel_launch(void* const* d_in, const int* in_sizes, int n_in,
                              void* d_out, int out_size)
{
    const float* X1    = (const float*)d_in[0];
    const float* X2    = (const float*)d_in[1];
    const float* Wq2   = (const float*)d_in[4];
    const float* bq2   = (const float*)d_in[5];
    const float* Wk2   = (const float*)d_in[8];
    const float* bk2   = (const float*)d_in[9];
    const float* Wv    = (const float*)d_in[10];
    const float* bv    = (const float*)d_in[11];
    const float* alpha = (const float*)d_in[12];
    float* out = (float*)d_out;

    float *Q2, *K2, *V, *P, *vc, *corr;
    cudaGetSymbolAddress((void**)&Q2,   g_Q2);
    cudaGetSymbolAddress((void**)&K2,   g_K2);
    cudaGetSymbolAddress((void**)&V,    g_V);
    cudaGetSymbolAddress((void**)&P,    g_P);
    cudaGetSymbolAddress((void**)&vc,   g_vconst);
    cudaGetSymbolAddress((void**)&corr, g_corr);

    const size_t sSD = (size_t)SEQ * DIM;   // per-batch stride of [S,D] tensors
    const size_t sSS = (size_t)SEQ * SEQ;   // per-batch stride of scores

    // 1) per-batch V constant: X1 @ Wv[:D] + bv
    vconst_kernel<<<dim3(DIM / 256, BATCH), 256>>>(X1, Wv, bv, vc);

    // 2) projections: Q2, K2, V (V adds per-batch vconst as bias)
    dim3 gproj(DIM / BN, SEQ / BM, BATCH);
    sgemm_nn<<<gproj, 256>>>(X2, Wq2, Q2, bq2, DIM, DIM, 1.f, sSD, 0, sSD, 0);
    sgemm_nn<<<gproj, 256>>>(X2, Wk2, K2, bk2, DIM, DIM, 1.f, sSD, 0, sSD, 0);
    sgemm_nn<<<gproj, 256>>>(X2, Wv + (size_t)DIM * DIM, V, vc,
                             DIM, DIM, 1.f, sSD, 0, sSD, DIM);

    // 3) correction vector: -(alpha/S) * colsum(V)
    colsum_kernel<<<dim3(DIM / 256, BATCH), 256>>>(V, alpha, corr);

    // 4) scores: P = (Q2 @ K2^T) / sqrt(D)
    sgemm_nt<<<dim3(SEQ / BN, SEQ / BM, BATCH), 256>>>(
        Q2, K2, P, SEQ, DIM, 0.03125f, sSD, sSD, sSS);

    // 5) row softmax in place
    softmax_kernel<<<BATCH * SEQ, 256>>>(P);

    // 6) out = P @ V + corr  (corr already carries the -alpha/S factor)
    sgemm_nn<<<dim3(DIM / BN, SEQ / BM, BATCH), 256>>>(
        P, V, out, corr, DIM, SEQ, 1.f, sSS, sSD, sSD, DIM);
}

// round 3
// speedup vs baseline: 1.0002x; 1.0002x over previous
#include <cuda_runtime.h>
#include <cuda_bf16.h>
#include <cstddef>

// Problem constants
#define BATCH 8
#define SEQ   2048
#define DIM   1024

// ---------------------------------------------------------------------------
// Scratch (allocation-free: __device__ globals)
// ---------------------------------------------------------------------------
__device__ float g_Q2[(size_t)BATCH * SEQ * DIM];           // 64 MB
__device__ float g_K2[(size_t)BATCH * SEQ * DIM];           // 64 MB
__device__ float g_V [(size_t)BATCH * SEQ * DIM];           // 64 MB
__device__ float g_P [(size_t)BATCH * SEQ * SEQ];           // 134 MB (scores/probs)
__device__ float g_vconst[BATCH * DIM];
__device__ float g_corr  [BATCH * DIM];

// ---------------------------------------------------------------------------
// vconst[b,n] = X1[b,:] @ Wv[0:D, n] + bv[n]
// grid (DIM/256, BATCH), block 256
// ---------------------------------------------------------------------------
__global__ __launch_bounds__(256) void vconst_kernel(
    const float* __restrict__ X1, const float* __restrict__ Wv,
    const float* __restrict__ bv, float* __restrict__ vconst)
{
    int n = blockIdx.x * 256 + threadIdx.x;
    int b = blockIdx.y;
    const float* x = X1 + b * DIM;
    float acc = bv[n];
    #pragma unroll 8
    for (int d = 0; d < DIM; d++)
        acc += x[d] * Wv[(size_t)d * DIM + n];
    vconst[b * DIM + n] = acc;
}

// ---------------------------------------------------------------------------
// corr[b,n] = -(alpha/SEQ) * sum_k V[b,k,n]
// grid (DIM/256, BATCH), block 256
// ---------------------------------------------------------------------------
__global__ __launch_bounds__(256) void colsum_kernel(
    const float* __restrict__ V, const float* __restrict__ alpha,
    float* __restrict__ corr)
{
    int n = blockIdx.x * 256 + threadIdx.x;
    int b = blockIdx.y;
    const float* p = V + (size_t)b * SEQ * DIM + n;
    float s0 = 0.f, s1 = 0.f, s2 = 0.f, s3 = 0.f;
    #pragma unroll 4
    for (int k = 0; k < SEQ; k += 4) {
        s0 += p[(size_t)(k + 0) * DIM];
        s1 += p[(size_t)(k + 1) * DIM];
        s2 += p[(size_t)(k + 2) * DIM];
        s3 += p[(size_t)(k + 3) * DIM];
    }
    corr[b * DIM + n] = -(alpha[0] / (float)SEQ) * ((s0 + s1) + (s2 + s3));
}

// ---------------------------------------------------------------------------
// Tiled SGEMM, 128x128 block tile, BK=16, 8x8 per thread, 256 threads.
// C = scale * (A @ B) + bias_row   (bias may be null -> 0)
// NN: A [M,K] row-major, B [K,N] row-major
// Batch via blockIdx.z with element strides sA/sB/sC/sBias.
// All dims assumed divisible by tile sizes (true for this problem).
// ---------------------------------------------------------------------------
#define BM 128
#define BN 128
#define BK 16
#define TM 8
#define TN 8
#define PAD 4

__global__ __launch_bounds__(256) void sgemm_nn(
    const float* __restrict__ A, const float* __restrict__ B,
    float* __restrict__ C, const float* __restrict__ bias,
    int N, int K, float scale,
    size_t sA, size_t sB, size_t sC, size_t sBias)
{
    __shared__ float As[BK][BM + PAD];
    __shared__ float Bs[BK][BN + PAD];

    const int z = blockIdx.z;
    A += (size_t)z * sA;
    B += (size_t)z * sB;
    C += (size_t)z * sC;
    const float* biasp = bias ? bias + (size_t)z * sBias : nullptr;

    const int tid  = threadIdx.x;
    const int brow = blockIdx.y * BM;
    const int bcol = blockIdx.x * BN;
    const int tr = (tid >> 4) * TM;   // 0..120
    const int tc = (tid & 15) * TN;   // 0..120

    // A-tile load mapping (transpose into smem): 128 rows x 16 cols
    const int a_row  = tid >> 2;        // 0..63 (two iters: +64)
    const int a_col4 = (tid & 3) * 4;   // 0,4,8,12
    // B-tile load mapping (direct float4): 16 rows x 128 cols
    const int b_row  = tid >> 5;        // 0..7 (two iters: +8)
    const int b_col4 = (tid & 31) * 4;  // 0..124

    float acc[TM][TN];
    #pragma unroll
    for (int i = 0; i < TM; i++)
        #pragma unroll
        for (int j = 0; j < TN; j++) acc[i][j] = 0.f;

    for (int k0 = 0; k0 < K; k0 += BK) {
        #pragma unroll
        for (int it = 0; it < 2; it++) {
            int r = a_row + it * 64;
            float4 v = *(const float4*)(A + (size_t)(brow + r) * K + k0 + a_col4);
            As[a_col4 + 0][r] = v.x;
            As[a_col4 + 1][r] = v.y;
            As[a_col4 + 2][r] = v.z;
            As[a_col4 + 3][r] = v.w;
        }
        #pragma unroll
        for (int it = 0; it < 2; it++) {
            int r = b_row + it * 8;
            *(float4*)(&Bs[r][b_col4]) =
                *(const float4*)(B + (size_t)(k0 + r) * N + bcol + b_col4);
        }
        __syncthreads();

        #pragma unroll
        for (int kk = 0; kk < BK; kk++) {
            float a[TM], bb[TN];
            #pragma unroll
            for (int i = 0; i < TM; i++) a[i] = As[kk][tr + i];
            #pragma unroll
            for (int j = 0; j < TN; j++) bb[j] = Bs[kk][tc + j];
            #pragma unroll
            for (int i = 0; i < TM; i++)
                #pragma unroll
                for (int j = 0; j < TN; j++)
                    acc[i][j] += a[i] * bb[j];
        }
        __syncthreads();
    }

    float bvreg[TN];
    #pragma unroll
    for (int j = 0; j < TN; j++)
        bvreg[j] = biasp ? biasp[bcol + tc + j] : 0.f;

    #pragma unroll
    for (int i = 0; i < TM; i++) {
        size_t crow = (size_t)(brow + tr + i) * N + bcol + tc;
        #pragma unroll
        for (int jj = 0; jj < TN; jj += 4) {
            float4 o;
            o.x = fmaf(acc[i][jj + 0], scale, bvreg[jj + 0]);
            o.y = fmaf(acc[i][jj + 1], scale, bvreg[jj + 1]);
            o.z = fmaf(acc[i][jj + 2], scale, bvreg[jj + 2]);
            o.w = fmaf(acc[i][jj + 3], scale, bvreg[jj + 3]);
            *(float4*)(C + crow + jj) = o;
        }
    }
}

// NT variant: C[i,j] = scale * sum_d A[i,d]*B[j,d]   (both row-major [.,K])
__global__ __launch_bounds__(256) void sgemm_nt(
    const float* __restrict__ A, const float* __restrict__ B,
    float* __restrict__ C,
    int N, int K, float scale,
    size_t sA, size_t sB, size_t sC)
{
    __shared__ float As[BK][BM + PAD];
    __shared__ float Bs[BK][BN + PAD];

    const int z = blockIdx.z;
    A += (size_t)z * sA;
    B += (size_t)z * sB;
    C += (size_t)z * sC;

    const int tid  = threadIdx.x;
    const int brow = blockIdx.y * BM;
    const int bcol = blockIdx.x * BN;
    const int tr = (tid >> 4) * TM;
    const int tc = (tid & 15) * TN;

    const int l_row  = tid >> 2;        // 0..63
    const int l_col4 = (tid & 3) * 4;   // 0,4,8,12

    float acc[TM][TN];
    #pragma unroll
    for (int i = 0; i < TM; i++)
        #pragma unroll
        for (int j = 0; j < TN; j++) acc[i][j] = 0.f;

    for (int k0 = 0; k0 < K; k0 += BK) {
        #pragma unroll
        for (int it = 0; it < 2; it++) {
            int r = l_row + it * 64;
            float4 v = *(const float4*)(A + (size_t)(brow + r) * K + k0 + l_col4);
            As[l_col4 + 0][r] = v.x;
            As[l_col4 + 1][r] = v.y;
            As[l_col4 + 2][r] = v.z;
            As[l_col4 + 3][r] = v.w;
        }
        #pragma unroll
        for (int it = 0; it < 2; it++) {
            int r = l_row + it * 64;
            float4 v = *(const float4*)(B + (size_t)(bcol + r) * K + k0 + l_col4);
            Bs[l_col4 + 0][r] = v.x;
            Bs[l_col4 + 1][r] = v.y;
            Bs[l_col4 + 2][r] = v.z;
            Bs[l_col4 + 3][r] = v.w;
        }
        __syncthreads();

        #pragma unroll
        for (int kk = 0; kk < BK; kk++) {
            float a[TM], bb[TN];
            #pragma unroll
            for (int i = 0; i < TM; i++) a[i] = As[kk][tr + i];
            #pragma unroll
            for (int j = 0; j < TN; j++) bb[j] = Bs[kk][tc + j];
            #pragma unroll
            for (int i = 0; i < TM; i++)
                #pragma unroll
                for (int j = 0; j < TN; j++)
                    acc[i][j] += a[i] * bb[j];
        }
        __syncthreads();
    }

    #pragma unroll
    for (int i = 0; i < TM; i++) {
        size_t crow = (size_t)(brow + tr + i) * N + bcol + tc;
        #pragma unroll
        for (int jj = 0; jj < TN; jj += 4) {
            float4 o;
            o.x = acc[i][jj + 0] * scale;
            o.y = acc[i][jj + 1] * scale;
            o.z = acc[i][jj + 2] * scale;
            o.w = acc[i][jj + 3] * scale;
            *(float4*)(C + crow + jj) = o;
        }
    }
}

// ---------------------------------------------------------------------------
// In-place row softmax over SEQ=2048 columns. One block (256 thr) per row.
// ---------------------------------------------------------------------------
__global__ __launch_bounds__(256) void softmax_kernel(float* __restrict__ P)
{
    float* row = P + (size_t)blockIdx.x * SEQ;
    const int tid = threadIdx.x;

    float v[8];
    float m = -1e30f;
    #pragma unroll
    for (int i = 0; i < 8; i++) {
        v[i] = row[tid + 256 * i];
        m = fmaxf(m, v[i]);
    }
    #pragma unroll
    for (int o = 16; o > 0; o >>= 1)
        m = fmaxf(m, __shfl_xor_sync(0xFFFFFFFFu, m, o));

    __shared__ float redm[8];
    __shared__ float reds[8];
    if ((tid & 31) == 0) redm[tid >> 5] = m;
    __syncthreads();
    m = redm[0];
    #pragma unroll
    for (int i = 1; i < 8; i++) m = fmaxf(m, redm[i]);

    float s = 0.f;
    #pragma unroll
    for (int i = 0; i < 8; i++) {
        v[i] = __expf(v[i] - m);
        s += v[i];
    }
    #pragma unroll
    for (int o = 16; o > 0; o >>= 1)
        s += __shfl_xor_sync(0xFFFFFFFFu, s, o);
    if ((tid & 31) == 0) reds[tid >> 5] = s;
    __syncthreads();
    s = reds[0];
    #pragma unroll
    for (int i = 1; i < 8; i++) s += reds[i];

    float inv = 1.f / s;
    #pragma unroll
    for (int i = 0; i < 8; i++)
        row[tid + 256 * i] = v[i] * inv;
}

// ---------------------------------------------------------------------------
// Launch
// Inputs (metadata order):
//  0 X1 [8,1024]   1 X2 [8,2048,1024]
//  2 Wq1 3 bq1 4 Wq2 5 bq2 6 Wk1 7 bk1 8 Wk2 9 bk2   (Wq1/bq1/Wk1/bk1 unused:
//     softmax of a row-constant score matrix is uniform 1/S)
//  10 Wv [2048,1024]  11 bv [1024]  12 alpha [1]
// Output: [8,2048,1024] float32
// ---------------------------------------------------------------------------
extern "C" void kernel_launch(void* const* d_in, const int* in_sizes, int n_in,
                              void* d_out, int out_size)
{
    const float* X1    = (const float*)d_in[0];
    const float* X2    = (const float*)d_in[1];
    const float* Wq2   = (const float*)d_in[4];
    const float* bq2   = (const float*)d_in[5];
    const float* Wk2   = (const float*)d_in[8];
    const float* bk2   = (const float*)d_in[9];
    const float* Wv    = (const float*)d_in[10];
    const float* bv    = (const float*)d_in[11];
    const float* alpha = (const float*)d_in[12];
    float* out = (float*)d_out;

    float *Q2, *K2, *V, *P, *vc, *corr;
    cudaGetSymbolAddress((void**)&Q2,   g_Q2);
    cudaGetSymbolAddress((void**)&K2,   g_K2);
    cudaGetSymbolAddress((void**)&V,    g_V);
    cudaGetSymbolAddress((void**)&P,    g_P);
    cudaGetSymbolAddress((void**)&vc,   g_vconst);
    cudaGetSymbolAddress((void**)&corr, g_corr);

    const size_t sSD = (size_t)SEQ * DIM;   // per-batch stride of [S,D] tensors
    const size_t sSS = (size_t)SEQ * SEQ;   // per-batch stride of scores

    // 1) per-batch V constant: X1 @ Wv[:D] + bv
    vconst_kernel<<<dim3(DIM / 256, BATCH), 256>>>(X1, Wv, bv, vc);

    // 2) projections: Q2, K2, V (V adds per-batch vconst as bias)
    dim3 gproj(DIM / BN, SEQ / BM, BATCH);
    sgemm_nn<<<gproj, 256>>>(X2, Wq2, Q2, bq2, DIM, DIM, 1.f, sSD, 0, sSD, 0);
    sgemm_nn<<<gproj, 256>>>(X2, Wk2, K2, bk2, DIM, DIM, 1.f, sSD, 0, sSD, 0);
    sgemm_nn<<<gproj, 256>>>(X2, Wv + (size_t)DIM * DIM, V, vc,
                             DIM, DIM, 1.f, sSD, 0, sSD, DIM);

    // 3) correction vector: -(alpha/S) * colsum(V)
    colsum_kernel<<<dim3(DIM / 256, BATCH), 256>>>(V, alpha, corr);

    // 4) scores: P = (Q2 @ K2^T) / sqrt(D)
    sgemm_nt<<<dim3(SEQ / BN, SEQ / BM, BATCH), 256>>>(
        Q2, K2, P, SEQ, DIM, 0.03125f, sSD, sSD, sSS);

    // 5) row softmax in place
    softmax_kernel<<<BATCH * SEQ, 256>>>(P);

    // 6) out = P @ V + corr  (corr already carries the -alpha/S factor)
    sgemm_nn<<<dim3(DIM / BN, SEQ / BM, BATCH), 256>>>(
        P, V, out, corr, DIM, SEQ, 1.f, sSS, sSD, sSD, DIM);
}